// round 3
// baseline (speedup 1.0000x reference)
#include <cuda_runtime.h>
#include <math.h>

// Problem constants: x is [B=4, M=2048, N=2048] float32.
// out[b,u,v] = sum_{p,q} x[b,p,q] * sin(pi*(2u+1)*p/(2M)) * cos(pi*(2v+1)*q/(2N))
#define NN2048 2048
#define BB4 4

// Scratch (device globals: allocation-free rule).
__device__ float g_C[NN2048 * NN2048];                     // C[v,q] = cos(pi*(2v+1)*q/4096)
__device__ float g_S[NN2048 * NN2048];                     // S[u,p] = sin(pi*(2u+1)*p/4096)
__device__ float g_T[(size_t)BB4 * NN2048 * NN2048];       // intermediate t[b,p,v]

// -------------------------------------------------------------------------
// Basis generation. (2v+1)*q <= 4095*2047 < 2^24 so the fp32 argument is
// exact; cospif/sinpif do proper pi-based range reduction (≈1 ulp).
// -------------------------------------------------------------------------
__global__ void gen_basis_kernel() {
    int idx = blockIdx.x * blockDim.x + threadIdx.x;
    if (idx >= NN2048 * NN2048) return;
    int v = idx >> 11;          // / 2048
    int q = idx & 2047;         // % 2048
    float a = (float)((2 * v + 1) * q) * (1.0f / 4096.0f);
    g_C[idx] = cospif(a);
    g_S[idx] = sinpif(a);
}

// -------------------------------------------------------------------------
// Tiled SGEMM: 128x128 block tile, BK=8, 256 threads, 8x8 register microtile.
//   BT = true :  Cm[i,j] = sum_k A[i,k] * Bm[j,k]   (both K-contiguous, "NT")
//   BT = false:  Cm[i,j] = sum_k A[i,k] * Bm[k,j]   ("NN")
// Batched over blockIdx.z with per-operand strides (stride 0 = shared operand).
// All dims are multiples of 128 -> no bounds checks.
// -------------------------------------------------------------------------
template <bool BT>
__global__ void __launch_bounds__(256)
sgemm_kernel(const float* __restrict__ A, const float* __restrict__ Bm,
             float* __restrict__ Cm, int M, int N, int K,
             size_t strideA, size_t strideB, size_t strideC)
{
    __shared__ float As[8][132];   // stride 132 (multiple of 4): conflict-free
    __shared__ float Bs[8][132];   // scatter stores + aligned float4 access

    A  += (size_t)blockIdx.z * strideA;
    Bm += (size_t)blockIdx.z * strideB;
    Cm += (size_t)blockIdx.z * strideC;

    const int tid  = threadIdx.x;
    const int brow = blockIdx.y * 128;
    const int bcol = blockIdx.x * 128;
    const int tx   = tid & 15;     // 16 column groups
    const int ty   = tid >> 4;     // 16 row groups

    // Tile-load indices: 128 rows x 8 k-cols = 256 float4, one per thread.
    const int lrow = tid >> 1;
    const int lcol = (tid & 1) << 2;

    float acc[8][8];
#pragma unroll
    for (int i = 0; i < 8; ++i)
#pragma unroll
        for (int j = 0; j < 8; ++j) acc[i][j] = 0.0f;

    for (int k0 = 0; k0 < K; k0 += 8) {
        // A tile: [128 rows x 8 k], transpose-scatter into As[k][row]
        float4 av = *(const float4*)(A + (size_t)(brow + lrow) * K + k0 + lcol);
        As[lcol + 0][lrow] = av.x;
        As[lcol + 1][lrow] = av.y;
        As[lcol + 2][lrow] = av.z;
        As[lcol + 3][lrow] = av.w;

        if (BT) {
            // B tile: [128 n-rows x 8 k], transpose-scatter into Bs[k][n]
            float4 bv = *(const float4*)(Bm + (size_t)(bcol + lrow) * K + k0 + lcol);
            Bs[lcol + 0][lrow] = bv.x;
            Bs[lcol + 1][lrow] = bv.y;
            Bs[lcol + 2][lrow] = bv.z;
            Bs[lcol + 3][lrow] = bv.w;
        } else {
            // B tile: [8 k-rows x 128 n], direct float4 into Bs[k][n]
            const int kr = tid >> 5;
            const int nc = (tid & 31) << 2;
            float4 bv = *(const float4*)(Bm + (size_t)(k0 + kr) * N + bcol + nc);
            *(float4*)&Bs[kr][nc] = bv;
        }
        __syncthreads();

#pragma unroll
        for (int kk = 0; kk < 8; ++kk) {
            float a[8], b[8];
            *(float4*)&a[0] = *(const float4*)&As[kk][ty * 8];
            *(float4*)&a[4] = *(const float4*)&As[kk][ty * 8 + 4];
            *(float4*)&b[0] = *(const float4*)&Bs[kk][tx * 8];
            *(float4*)&b[4] = *(const float4*)&Bs[kk][tx * 8 + 4];
#pragma unroll
            for (int i = 0; i < 8; ++i)
#pragma unroll
                for (int j = 0; j < 8; ++j)
                    acc[i][j] = fmaf(a[i], b[j], acc[i][j]);
        }
        __syncthreads();
    }

#pragma unroll
    for (int i = 0; i < 8; ++i) {
        float* outp = Cm + (size_t)(brow + ty * 8 + i) * N + bcol + tx * 8;
        float4 v0 = make_float4(acc[i][0], acc[i][1], acc[i][2], acc[i][3]);
        float4 v1 = make_float4(acc[i][4], acc[i][5], acc[i][6], acc[i][7]);
        *(float4*)outp       = v0;
        *(float4*)(outp + 4) = v1;
    }
}

// -------------------------------------------------------------------------
// Launch: gen basis -> T = X @ C^T (NT) -> Out_b = S @ T_b (NN).
// Graph-capturable: kernel launches only, no alloc, no sync.
// -------------------------------------------------------------------------
extern "C" void kernel_launch(void* const* d_in, const int* in_sizes, int n_in,
                              void* d_out, int out_size)
{
    const float* x   = (const float*)d_in[0];
    float*       out = (float*)d_out;

    float *pC, *pS, *pT;
    cudaGetSymbolAddress((void**)&pC, g_C);
    cudaGetSymbolAddress((void**)&pS, g_S);
    cudaGetSymbolAddress((void**)&pT, g_T);

    const size_t plane = (size_t)NN2048 * NN2048;

    // 1) Basis matrices (regenerated every call: deterministic, cheap ~8.4M elems)
    gen_basis_kernel<<<(NN2048 * NN2048 + 255) / 256, 256>>>();

    // 2) t[b,p,v] = sum_q x[b,p,q] * C[v,q]   ("NT": both K-contiguous)
    //    grid: 16 col-tiles x 16 row-tiles x 4 batches
    sgemm_kernel<true><<<dim3(16, 16, BB4), 256>>>(
        x, pC, pT, NN2048, NN2048, NN2048,
        /*strideA=*/plane, /*strideB=*/0, /*strideC=*/plane);

    // 3) out[b,u,v] = sum_p S[u,p] * t[b,p,v]   ("NN")
    sgemm_kernel<false><<<dim3(16, 16, BB4), 256>>>(
        pS, pT, out, NN2048, NN2048, NN2048,
        /*strideA=*/0, /*strideB=*/plane, /*strideC=*/plane);
}

// round 5
// speedup vs baseline: 3.5328x; 3.5328x over previous
#include <cuda_runtime.h>
#include <cuda_bf16.h>
#include <stdint.h>
#include <math.h>

// x: [B=4, 2048, 2048] fp32.
// out[b,u,v] = sum_{p,q} x[b,p,q] * sin(pi*(2u+1)*p/4096) * cos(pi*(2v+1)*q/4096)
// Stage 1: T'[b,v,p] = sum_q C[v,q] * X[b,p,q]      (NT GEMM, K-major both)
// Stage 2: out[b,u,v] = sum_p S[u,p] * T'[b,v,p]    (NT GEMM, K-major both)
// fp32 operands split into bf16 hi+lo; 3 HMMA terms per K-chunk (hh + hl + lh).
// NOTE: tcgen05 is rejected at this toolchain's compute_103 PTX target, so we
// use base-ISA tensor cores: mma.sync.m16n8k16 bf16 + ldmatrix + cp.async.

#define NQ 2048
#define NB 4

// ---------------- device scratch (allocation-free rule) ----------------
__device__ __align__(256) __nv_bfloat16 g_Chi[NQ * NQ];
__device__ __align__(256) __nv_bfloat16 g_Clo[NQ * NQ];
__device__ __align__(256) __nv_bfloat16 g_Shi[NQ * NQ];
__device__ __align__(256) __nv_bfloat16 g_Slo[NQ * NQ];
__device__ __align__(256) __nv_bfloat16 g_Xhi[(size_t)NB * NQ * NQ];
__device__ __align__(256) __nv_bfloat16 g_Xlo[(size_t)NB * NQ * NQ];
__device__ __align__(256) __nv_bfloat16 g_Thi[(size_t)NB * NQ * NQ];
__device__ __align__(256) __nv_bfloat16 g_Tlo[(size_t)NB * NQ * NQ];

// ---------------- helpers ----------------
__device__ __forceinline__ uint32_t smem_u32(const void* p) {
    uint32_t a;
    asm("{ .reg .u64 t; cvta.to.shared.u64 t, %1; cvt.u32.u64 %0, t; }"
        : "=r"(a) : "l"(p));
    return a;
}
__device__ __forceinline__ uint32_t sw128(uint32_t off) { return off ^ ((off >> 3) & 0x70); }

#define CP16(saddr, gptr) \
    asm volatile("cp.async.cg.shared.global [%0], [%1], 16;" \
                 :: "r"(saddr), "l"(gptr) : "memory")
#define CP_COMMIT() asm volatile("cp.async.commit_group;" ::: "memory")
#define CP_WAIT1() asm volatile("cp.async.wait_group 1;" ::: "memory")
#define CP_WAIT0() asm volatile("cp.async.wait_group 0;" ::: "memory")

#define LDM4(d, addr) \
    asm volatile("ldmatrix.sync.aligned.m8n8.x4.shared.b16 {%0,%1,%2,%3}, [%4];" \
                 : "=r"((d)[0]), "=r"((d)[1]), "=r"((d)[2]), "=r"((d)[3]) : "r"(addr))

#define MMA16816(c, a, b0v, b1v) \
    asm volatile("mma.sync.aligned.m16n8k16.row.col.f32.bf16.bf16.f32 " \
                 "{%0,%1,%2,%3}, {%4,%5,%6,%7}, {%8,%9}, {%0,%1,%2,%3};" \
                 : "+f"((c)[0]), "+f"((c)[1]), "+f"((c)[2]), "+f"((c)[3]) \
                 : "r"((a)[0]), "r"((a)[1]), "r"((a)[2]), "r"((a)[3]), \
                   "r"(b0v), "r"(b1v))

// ---------------- prologue kernels ----------------
__global__ void gen_basis_split() {
    int idx = blockIdx.x * blockDim.x + threadIdx.x;
    if (idx >= NQ * NQ) return;
    int v = idx >> 11, q = idx & 2047;
    float a = (float)((2 * v + 1) * q) * (1.0f / 4096.0f);
    float c = cospif(a), s = sinpif(a);
    __nv_bfloat16 ch = __float2bfloat16(c);
    g_Chi[idx] = ch;
    g_Clo[idx] = __float2bfloat16(c - __bfloat162float(ch));
    __nv_bfloat16 sh = __float2bfloat16(s);
    g_Shi[idx] = sh;
    g_Slo[idx] = __float2bfloat16(s - __bfloat162float(sh));
}

__global__ void split_x(const float* __restrict__ x) {
    size_t i = (size_t)blockIdx.x * blockDim.x + threadIdx.x;   // one float4 per thread
    const size_t total4 = (size_t)NB * NQ * NQ / 4;
    if (i >= total4) return;
    float4 v = ((const float4*)x)[i];
    float f[4] = {v.x, v.y, v.z, v.w};
    __nv_bfloat16 h[4], l[4];
#pragma unroll
    for (int k = 0; k < 4; ++k) {
        h[k] = __float2bfloat16(f[k]);
        l[k] = __float2bfloat16(f[k] - __bfloat162float(h[k]));
    }
    __nv_bfloat162 h01 = __halves2bfloat162(h[0], h[1]);
    __nv_bfloat162 h23 = __halves2bfloat162(h[2], h[3]);
    __nv_bfloat162 l01 = __halves2bfloat162(l[0], l[1]);
    __nv_bfloat162 l23 = __halves2bfloat162(l[2], l[3]);
    uint2 uh, ul;
    uh.x = *(uint32_t*)&h01; uh.y = *(uint32_t*)&h23;
    ul.x = *(uint32_t*)&l01; ul.y = *(uint32_t*)&l23;
    ((uint2*)g_Xhi)[i] = uh;
    ((uint2*)g_Xlo)[i] = ul;
}

// ---------------- main GEMM kernel ----------------
// Block tile 128x128, BK=64. SMEM buffer (64KB): Ahi | Alo | Bhi | Blo tiles,
// each 128 rows x 64 bf16 (128B rows, SW128 swizzle). Double-buffered.
#define TILE_BYTES 16384
#define BUF_BYTES  (4 * TILE_BYTES)          // 65536
#define SMEM_TOTAL (2 * BUF_BYTES)           // 131072
#define NCHUNK     (NQ / 64)                 // 32

__device__ __forceinline__ void load_chunk(uint32_t sbuf,
                                           const __nv_bfloat16* __restrict__ Ah,
                                           const __nv_bfloat16* __restrict__ Al,
                                           const __nv_bfloat16* __restrict__ Bh,
                                           const __nv_bfloat16* __restrict__ Bl,
                                           int m0, int n0, int k0, int tid) {
#pragma unroll
    for (int j = 0; j < 4; ++j) {
        int e = tid + 256 * j;           // 0..1023
        int r = e >> 3, c = e & 7;       // row 0..127, 16B chunk 0..7
        uint32_t soff = sw128((uint32_t)(r * 128 + c * 16));
        size_t gA = (size_t)(m0 + r) * NQ + k0 + c * 8;
        size_t gB = (size_t)(n0 + r) * NQ + k0 + c * 8;
        CP16(sbuf + soff,                  Ah + gA);
        CP16(sbuf + TILE_BYTES + soff,     Al + gA);
        CP16(sbuf + 2 * TILE_BYTES + soff, Bh + gB);
        CP16(sbuf + 3 * TILE_BYTES + soff, Bl + gB);
    }
}

// ldmatrix lane-address helpers. A tile (m x k): x4 sub-tiles ordered
// (m0-7,k0-7),(m8-15,k0-7),(m0-7,k8-15),(m8-15,k8-15) -> a0..a3 of mma.
__device__ __forceinline__ uint32_t a_addr(uint32_t buf, int mt, int s, int lane) {
    int sub = lane >> 3;
    int r = mt + ((sub & 1) << 3) + (lane & 7);
    int c = 2 * s + (sub >> 1);
    return buf + sw128((uint32_t)(r * 128 + c * 16));
}
// B tile (n x k): sub-tiles (n0-7,k0-7),(n0-7,k8-15),(n8-15,k0-7),(n8-15,k8-15)
// -> regs {b0,b1} for n0-7 and {b0,b1} for n8-15.
__device__ __forceinline__ uint32_t b_addr(uint32_t buf, int nt, int s, int lane) {
    int sub = lane >> 3;
    int r = nt + ((sub >> 1) << 3) + (lane & 7);
    int c = 2 * s + (sub & 1);
    return buf + sw128((uint32_t)(r * 128 + c * 16));
}

__device__ __forceinline__ void store_split(__nv_bfloat16* __restrict__ H,
                                            __nv_bfloat16* __restrict__ L,
                                            size_t off, float x, float y) {
    __nv_bfloat16 hx = __float2bfloat16(x);
    __nv_bfloat16 hy = __float2bfloat16(y);
    __nv_bfloat16 lx = __float2bfloat16(x - __bfloat162float(hx));
    __nv_bfloat16 ly = __float2bfloat16(y - __bfloat162float(hy));
    __nv_bfloat162 hp = __halves2bfloat162(hx, hy);
    __nv_bfloat162 lp = __halves2bfloat162(lx, ly);
    *(__nv_bfloat162*)(H + off) = hp;
    *(__nv_bfloat162*)(L + off) = lp;
}

template <int STAGE>
__global__ void __launch_bounds__(256, 1)
idsct_hmma_kernel(const __nv_bfloat16* __restrict__ Ahi, const __nv_bfloat16* __restrict__ Alo,
                  const __nv_bfloat16* __restrict__ Bhi, const __nv_bfloat16* __restrict__ Blo,
                  __nv_bfloat16* __restrict__ OutHi, __nv_bfloat16* __restrict__ OutLo,
                  float* __restrict__ OutF) {
    extern __shared__ char smem[];
    const uint32_t sbase = smem_u32(smem);
    const int tid = threadIdx.x, wid = tid >> 5, lane = tid & 31;
    const int wm = wid & 1;          // 2 warp rows  -> 64 M each
    const int wn = wid >> 1;         // 4 warp cols  -> 32 N each
    const int m0 = blockIdx.y * 128;
    const int n0 = blockIdx.x * 128;
    const int b  = blockIdx.z;
    const size_t plane = (size_t)NQ * NQ;
    const __nv_bfloat16* Bh = Bhi + (size_t)b * plane;
    const __nv_bfloat16* Bl = Blo + (size_t)b * plane;

    float acc[4][4][4];              // [mi][ni][quad]
#pragma unroll
    for (int i = 0; i < 4; ++i)
#pragma unroll
        for (int j = 0; j < 4; ++j)
#pragma unroll
            for (int q = 0; q < 4; ++q) acc[i][j][q] = 0.0f;

    load_chunk(sbase, Ahi, Alo, Bh, Bl, m0, n0, 0, tid);
    CP_COMMIT();

    for (int ci = 0; ci < NCHUNK; ++ci) {
        const uint32_t cur = (uint32_t)(ci & 1);
        if (ci + 1 < NCHUNK) {
            load_chunk(sbase + (1u - cur) * BUF_BYTES, Ahi, Alo, Bh, Bl,
                       m0, n0, (ci + 1) * 64, tid);
            CP_COMMIT();
            CP_WAIT1();
        } else {
            CP_WAIT0();
        }
        __syncthreads();

        const uint32_t bAh = sbase + cur * BUF_BYTES;
        const uint32_t bAl = bAh + TILE_BYTES;
        const uint32_t bBh = bAh + 2 * TILE_BYTES;
        const uint32_t bBl = bAh + 3 * TILE_BYTES;

#pragma unroll
        for (int s = 0; s < 4; ++s) {           // 4 k16 steps per BK=64
            uint32_t ah[4][4], al[4][4], bh[2][4], bl[2][4];
#pragma unroll
            for (int mi = 0; mi < 4; ++mi) {
                LDM4(ah[mi], a_addr(bAh, wm * 64 + mi * 16, s, lane));
                LDM4(al[mi], a_addr(bAl, wm * 64 + mi * 16, s, lane));
            }
#pragma unroll
            for (int nj = 0; nj < 2; ++nj) {
                LDM4(bh[nj], b_addr(bBh, wn * 32 + nj * 16, s, lane));
                LDM4(bl[nj], b_addr(bBl, wn * 32 + nj * 16, s, lane));
            }
#pragma unroll
            for (int mi = 0; mi < 4; ++mi)
#pragma unroll
                for (int ni = 0; ni < 4; ++ni) {
                    const int nj = ni >> 1, nh = (ni & 1) * 2;
                    MMA16816(acc[mi][ni], ah[mi], bh[nj][nh], bh[nj][nh + 1]);  // hh
                    MMA16816(acc[mi][ni], ah[mi], bl[nj][nh], bl[nj][nh + 1]);  // hl
                    MMA16816(acc[mi][ni], al[mi], bh[nj][nh], bh[nj][nh + 1]);  // lh
                }
        }
        __syncthreads();
    }

    // epilogue: c0,c1 = (row, col..col+1); c2,c3 = (row+8, col..col+1)
    const int rq = lane >> 2, cq = (lane & 3) * 2;
    const int rbase = m0 + wm * 64;
    const int cbase = n0 + wn * 32;
#pragma unroll
    for (int mi = 0; mi < 4; ++mi)
#pragma unroll
        for (int ni = 0; ni < 4; ++ni) {
            const int r0 = rbase + mi * 16 + rq;
            const int cc = cbase + ni * 8 + cq;
            const size_t off0 = ((size_t)b * NQ + r0) * NQ + cc;
            const size_t off1 = off0 + (size_t)8 * NQ;
            if (STAGE == 1) {
                store_split(OutHi, OutLo, off0, acc[mi][ni][0], acc[mi][ni][1]);
                store_split(OutHi, OutLo, off1, acc[mi][ni][2], acc[mi][ni][3]);
            } else {
                float2 v0 = make_float2(acc[mi][ni][0], acc[mi][ni][1]);
                float2 v1 = make_float2(acc[mi][ni][2], acc[mi][ni][3]);
                *(float2*)(OutF + off0) = v0;
                *(float2*)(OutF + off1) = v1;
            }
        }
}

// ---------------- launch ----------------
extern "C" void kernel_launch(void* const* d_in, const int* in_sizes, int n_in,
                              void* d_out, int out_size) {
    const float* x = (const float*)d_in[0];
    float* out = (float*)d_out;

    __nv_bfloat16 *pChi, *pClo, *pShi, *pSlo, *pXhi, *pXlo, *pThi, *pTlo;
    cudaGetSymbolAddress((void**)&pChi, g_Chi);
    cudaGetSymbolAddress((void**)&pClo, g_Clo);
    cudaGetSymbolAddress((void**)&pShi, g_Shi);
    cudaGetSymbolAddress((void**)&pSlo, g_Slo);
    cudaGetSymbolAddress((void**)&pXhi, g_Xhi);
    cudaGetSymbolAddress((void**)&pXlo, g_Xlo);
    cudaGetSymbolAddress((void**)&pThi, g_Thi);
    cudaGetSymbolAddress((void**)&pTlo, g_Tlo);

    cudaFuncSetAttribute(idsct_hmma_kernel<1>, cudaFuncAttributeMaxDynamicSharedMemorySize, SMEM_TOTAL);
    cudaFuncSetAttribute(idsct_hmma_kernel<2>, cudaFuncAttributeMaxDynamicSharedMemorySize, SMEM_TOTAL);

    // 1) basis + input split
    gen_basis_split<<<(NQ * NQ + 255) / 256, 256>>>();
    split_x<<<(int)(((size_t)NB * NQ * NQ / 4 + 255) / 256), 256>>>(x);

    // 2) T'[b,v,p] = sum_q C[v,q] X[b,p,q]   (A = C, B = X_b)
    idsct_hmma_kernel<1><<<dim3(16, 16, NB), 256, SMEM_TOTAL>>>(
        pChi, pClo, pXhi, pXlo, pThi, pTlo, nullptr);

    // 3) out[b,u,v] = sum_p S[u,p] T'[b,v,p] (A = S, B = T'_b)
    idsct_hmma_kernel<2><<<dim3(16, 16, NB), 256, SMEM_TOTAL>>>(
        pShi, pSlo, pThi, pTlo, nullptr, nullptr, out);
}

// round 6
// speedup vs baseline: 5.3977x; 1.5279x over previous
#include <cuda_runtime.h>
#include <cuda_bf16.h>
#include <stdint.h>
#include <math.h>

// x: [B=4, 2048, 2048] fp32.
// out[b,u,v] = sum_{p,q} x[b,p,q] * sin(pi*(2u+1)*p/4096) * cos(pi*(2v+1)*q/4096)
//
// Parity fold (one butterfly level), using
//   C[2047-v, q] = (-1)^q C[v,q],  S[2047-u, p] = -(-1)^p S[u,p]:
// Stage 1: E1[v',p] = sum_{qe} Ce[v',qe] Xe[p,qe],  O1[v',p] = sum_{qo} Co[v',qo] Xo[p,qo]
//          T'[v',p] = E1+O1,  T'[2047-v',p] = E1-O1      (v' in [0,1024))
// Stage 2: E2[u',v] = sum_{pe} Se[u',pe] Te[v,pe],  O2 = sum So[u',po] To[v,po]
//          out[u',v] = E2+O2,  out[2047-u',v] = O2-E2
// -> half the GEMM MACs of the unfolded form.
// fp32 operands split into bf16 hi+lo; 3 HMMA terms per k16 (hh + hl + lh).

#define NQ 2048
#define KH 1024
#define NB 4
typedef __nv_bfloat16 bf16;

// ---------------- device scratch (allocation-free rule) ----------------
__device__ __align__(256) bf16 g_Ce_h[KH * KH];
__device__ __align__(256) bf16 g_Ce_l[KH * KH];
__device__ __align__(256) bf16 g_Co_h[KH * KH];
__device__ __align__(256) bf16 g_Co_l[KH * KH];
__device__ __align__(256) bf16 g_Se_h[KH * KH];
__device__ __align__(256) bf16 g_Se_l[KH * KH];
__device__ __align__(256) bf16 g_So_h[KH * KH];
__device__ __align__(256) bf16 g_So_l[KH * KH];
__device__ __align__(256) bf16 g_Xe_h[(size_t)NB * NQ * KH];
__device__ __align__(256) bf16 g_Xe_l[(size_t)NB * NQ * KH];
__device__ __align__(256) bf16 g_Xo_h[(size_t)NB * NQ * KH];
__device__ __align__(256) bf16 g_Xo_l[(size_t)NB * NQ * KH];
__device__ __align__(256) bf16 g_Te_h[(size_t)NB * NQ * KH];
__device__ __align__(256) bf16 g_Te_l[(size_t)NB * NQ * KH];
__device__ __align__(256) bf16 g_To_h[(size_t)NB * NQ * KH];
__device__ __align__(256) bf16 g_To_l[(size_t)NB * NQ * KH];

// ---------------- helpers ----------------
__device__ __forceinline__ uint32_t smem_u32(const void* p) {
    uint32_t a;
    asm("{ .reg .u64 t; cvta.to.shared.u64 t, %1; cvt.u32.u64 %0, t; }"
        : "=r"(a) : "l"(p));
    return a;
}
__device__ __forceinline__ uint32_t sw128(uint32_t off) { return off ^ ((off >> 3) & 0x70); }

#define CP16(saddr, gptr) \
    asm volatile("cp.async.cg.shared.global [%0], [%1], 16;" \
                 :: "r"(saddr), "l"(gptr) : "memory")
#define CP_COMMIT() asm volatile("cp.async.commit_group;" ::: "memory")
#define CP_WAIT1() asm volatile("cp.async.wait_group 1;" ::: "memory")
#define CP_WAIT0() asm volatile("cp.async.wait_group 0;" ::: "memory")

#define LDM4(d, addr) \
    asm volatile("ldmatrix.sync.aligned.m8n8.x4.shared.b16 {%0,%1,%2,%3}, [%4];" \
                 : "=r"((d)[0]), "=r"((d)[1]), "=r"((d)[2]), "=r"((d)[3]) : "r"(addr))

#define MMA16816(c, a, b0v, b1v) \
    asm volatile("mma.sync.aligned.m16n8k16.row.col.f32.bf16.bf16.f32 " \
                 "{%0,%1,%2,%3}, {%4,%5,%6,%7}, {%8,%9}, {%0,%1,%2,%3};" \
                 : "+f"((c)[0]), "+f"((c)[1]), "+f"((c)[2]), "+f"((c)[3]) \
                 : "r"((a)[0]), "r"((a)[1]), "r"((a)[2]), "r"((a)[3]), \
                   "r"(b0v), "r"(b1v))

__device__ __forceinline__ void put_split(bf16* __restrict__ H, bf16* __restrict__ L,
                                          size_t off, float v) {
    bf16 h = __float2bfloat16(v);
    H[off] = h;
    L[off] = __float2bfloat16(v - __bfloat162float(h));
}

// ---------------- prologue kernels ----------------
__global__ void gen_basis_split() {
    int idx = blockIdx.x * blockDim.x + threadIdx.x;
    if (idx >= KH * KH) return;
    int v = idx >> 10, k = idx & 1023;
    // (2v+1)*(2k+1) <= 2047*2047 < 2^22: exact in fp32
    float ae = (float)((2 * v + 1) * (2 * k)) * (1.0f / 4096.0f);
    float ao = (float)((2 * v + 1) * (2 * k + 1)) * (1.0f / 4096.0f);
    float ce = cospif(ae), co = cospif(ao);
    float se = sinpif(ae), so = sinpif(ao);
    put_split(g_Ce_h, g_Ce_l, idx, ce);
    put_split(g_Co_h, g_Co_l, idx, co);
    put_split(g_Se_h, g_Se_l, idx, se);
    put_split(g_So_h, g_So_l, idx, so);
}

__global__ void split_x(const float* __restrict__ x) {
    size_t i = (size_t)blockIdx.x * blockDim.x + threadIdx.x;  // 8 floats / thread
    const size_t total = (size_t)NB * NQ * NQ / 8;
    if (i >= total) return;
    float4 v0 = ((const float4*)x)[2 * i];
    float4 v1 = ((const float4*)x)[2 * i + 1];
    float ev[4] = {v0.x, v0.z, v1.x, v1.z};
    float od[4] = {v0.y, v0.w, v1.y, v1.w};
    bf16 eh[4], el[4], oh[4], ol[4];
#pragma unroll
    for (int k = 0; k < 4; ++k) {
        eh[k] = __float2bfloat16(ev[k]);
        el[k] = __float2bfloat16(ev[k] - __bfloat162float(eh[k]));
        oh[k] = __float2bfloat16(od[k]);
        ol[k] = __float2bfloat16(od[k] - __bfloat162float(oh[k]));
    }
    uint2 ueh, uel, uoh, uol;
    { __nv_bfloat162 p0 = __halves2bfloat162(eh[0], eh[1]), p1 = __halves2bfloat162(eh[2], eh[3]);
      ueh.x = *(uint32_t*)&p0; ueh.y = *(uint32_t*)&p1; }
    { __nv_bfloat162 p0 = __halves2bfloat162(el[0], el[1]), p1 = __halves2bfloat162(el[2], el[3]);
      uel.x = *(uint32_t*)&p0; uel.y = *(uint32_t*)&p1; }
    { __nv_bfloat162 p0 = __halves2bfloat162(oh[0], oh[1]), p1 = __halves2bfloat162(oh[2], oh[3]);
      uoh.x = *(uint32_t*)&p0; uoh.y = *(uint32_t*)&p1; }
    { __nv_bfloat162 p0 = __halves2bfloat162(ol[0], ol[1]), p1 = __halves2bfloat162(ol[2], ol[3]);
      uol.x = *(uint32_t*)&p0; uol.y = *(uint32_t*)&p1; }
    ((uint2*)g_Xe_h)[i] = ueh;
    ((uint2*)g_Xe_l)[i] = uel;
    ((uint2*)g_Xo_h)[i] = uoh;
    ((uint2*)g_Xo_l)[i] = uol;
}

// ---------------- main GEMM kernel ----------------
// Block tile 128x128, BK=64, lda=ldb=KH=1024. SMEM buffer (64KB):
// Ahi | Alo | Bhi | Blo tiles, each 128 x 64 bf16 (128B rows, SW128).
// Double-buffered + 64KB fp32 E-stash. 32 chunks: 0-15 even operands (E pass),
// 16-31 odd operands (O pass).
#define TILE_BYTES 16384
#define BUF_BYTES  (4 * TILE_BYTES)                // 65536
#define STASH_OFF  (2 * BUF_BYTES)                 // 131072
#define SMEM_TOTAL (2 * BUF_BYTES + 65536)         // 196608
#define NCHUNK     32

__device__ __forceinline__ void load_chunk(uint32_t sbuf,
                                           const bf16* __restrict__ Ah,
                                           const bf16* __restrict__ Al,
                                           const bf16* __restrict__ Bh,
                                           const bf16* __restrict__ Bl,
                                           int m0, int n0, int k0, int tid) {
#pragma unroll
    for (int j = 0; j < 4; ++j) {
        int e = tid + 256 * j;           // 0..1023
        int r = e >> 3, c = e & 7;       // row 0..127, 16B chunk 0..7
        uint32_t soff = sw128((uint32_t)(r * 128 + c * 16));
        size_t gA = (size_t)(m0 + r) * KH + k0 + c * 8;
        size_t gB = (size_t)(n0 + r) * KH + k0 + c * 8;
        CP16(sbuf + soff,                  Ah + gA);
        CP16(sbuf + TILE_BYTES + soff,     Al + gA);
        CP16(sbuf + 2 * TILE_BYTES + soff, Bh + gB);
        CP16(sbuf + 3 * TILE_BYTES + soff, Bl + gB);
    }
}

__device__ __forceinline__ uint32_t a_addr(uint32_t buf, int mt, int s, int lane) {
    int sub = lane >> 3;
    int r = mt + ((sub & 1) << 3) + (lane & 7);
    int c = 2 * s + (sub >> 1);
    return buf + sw128((uint32_t)(r * 128 + c * 16));
}
__device__ __forceinline__ uint32_t b_addr(uint32_t buf, int nt, int s, int lane) {
    int sub = lane >> 3;
    int r = nt + ((sub >> 1) << 3) + (lane & 7);
    int c = 2 * s + (sub & 1);
    return buf + sw128((uint32_t)(r * 128 + c * 16));
}

template <int STAGE>
__global__ void __launch_bounds__(256, 1)
idsct_fold_kernel(const bf16* __restrict__ Aeh, const bf16* __restrict__ Ael,
                  const bf16* __restrict__ Aoh, const bf16* __restrict__ Aol,
                  const bf16* __restrict__ Beh, const bf16* __restrict__ Bel,
                  const bf16* __restrict__ Boh, const bf16* __restrict__ Bol,
                  bf16* __restrict__ Teh, bf16* __restrict__ Tel,
                  bf16* __restrict__ Toh, bf16* __restrict__ Tol,
                  float* __restrict__ OutF) {
    extern __shared__ char smem[];
    const uint32_t sbase = smem_u32(smem);
    float4* stash4 = (float4*)(smem + STASH_OFF);
    const int tid = threadIdx.x, wid = tid >> 5, lane = tid & 31;
    const int wm = wid & 1;          // 2 warp rows  -> 64 M each
    const int wn = wid >> 1;         // 4 warp cols  -> 32 N each
    const int m0 = blockIdx.y * 128; // [0,1024)
    const int n0 = blockIdx.x * 128; // [0,2048)
    const int b  = blockIdx.z;
    const size_t plane = (size_t)NQ * KH;
    const bf16* pBeh = Beh + (size_t)b * plane;
    const bf16* pBel = Bel + (size_t)b * plane;
    const bf16* pBoh = Boh + (size_t)b * plane;
    const bf16* pBol = Bol + (size_t)b * plane;

    float acc[4][4][4];              // [mi][ni][quad]
#pragma unroll
    for (int i = 0; i < 4; ++i)
#pragma unroll
        for (int j = 0; j < 4; ++j)
#pragma unroll
            for (int q = 0; q < 4; ++q) acc[i][j][q] = 0.0f;

    load_chunk(sbase, Aeh, Ael, pBeh, pBel, m0, n0, 0, tid);
    CP_COMMIT();

    for (int ci = 0; ci < NCHUNK; ++ci) {
        const uint32_t cur = (uint32_t)(ci & 1);
        if (ci + 1 < NCHUNK) {
            const int nc = ci + 1;
            const int k0n = (nc & 15) * 64;
            if (nc < 16)
                load_chunk(sbase + (1u - cur) * BUF_BYTES, Aeh, Ael, pBeh, pBel, m0, n0, k0n, tid);
            else
                load_chunk(sbase + (1u - cur) * BUF_BYTES, Aoh, Aol, pBoh, pBol, m0, n0, k0n, tid);
            CP_COMMIT();
            CP_WAIT1();
        } else {
            CP_WAIT0();
        }
        __syncthreads();

        const uint32_t bAh = sbase + cur * BUF_BYTES;
        const uint32_t bAl = bAh + TILE_BYTES;
        const uint32_t bBh = bAh + 2 * TILE_BYTES;
        const uint32_t bBl = bAh + 3 * TILE_BYTES;

#pragma unroll
        for (int s = 0; s < 4; ++s) {           // 4 k16 steps per BK=64
            uint32_t ah[4][4], al[4][4], bh[2][4], bl[2][4];
#pragma unroll
            for (int mi = 0; mi < 4; ++mi) {
                LDM4(ah[mi], a_addr(bAh, wm * 64 + mi * 16, s, lane));
                LDM4(al[mi], a_addr(bAl, wm * 64 + mi * 16, s, lane));
            }
#pragma unroll
            for (int nj = 0; nj < 2; ++nj) {
                LDM4(bh[nj], b_addr(bBh, wn * 32 + nj * 16, s, lane));
                LDM4(bl[nj], b_addr(bBl, wn * 32 + nj * 16, s, lane));
            }
#pragma unroll
            for (int mi = 0; mi < 4; ++mi)
#pragma unroll
                for (int ni = 0; ni < 4; ++ni) {
                    const int nj = ni >> 1, nh = (ni & 1) * 2;
                    MMA16816(acc[mi][ni], ah[mi], bh[nj][nh], bh[nj][nh + 1]);  // hh
                    MMA16816(acc[mi][ni], ah[mi], bl[nj][nh], bl[nj][nh + 1]);  // hl
                    MMA16816(acc[mi][ni], al[mi], bh[nj][nh], bh[nj][nh + 1]);  // lh
                }
        }

        if (ci == 15) {
            // stash E tile (per-thread private slices, conflict-free layout)
#pragma unroll
            for (int mi = 0; mi < 4; ++mi)
#pragma unroll
                for (int ni = 0; ni < 4; ++ni) {
                    stash4[(mi * 4 + ni) * 256 + tid] =
                        make_float4(acc[mi][ni][0], acc[mi][ni][1],
                                    acc[mi][ni][2], acc[mi][ni][3]);
#pragma unroll
                    for (int q = 0; q < 4; ++q) acc[mi][ni][q] = 0.0f;
                }
        }
        __syncthreads();
    }

    // epilogue. acc = O tile, stash = E tile.
    // quad mapping: c0,c1 = (row rq, cols cq,cq+1); c2,c3 = (row rq+8, same cols)
    const int rq = lane >> 2, cq = (lane & 3) * 2;
    const int rbase = m0 + wm * 64;   // row in [0,1024)
    const int cbase = n0 + wn * 32;
#pragma unroll
    for (int mi = 0; mi < 4; ++mi)
#pragma unroll
        for (int ni = 0; ni < 4; ++ni) {
            float4 e4 = stash4[(mi * 4 + ni) * 256 + tid];
            const float o0 = acc[mi][ni][0], o1 = acc[mi][ni][1];
            const float o2 = acc[mi][ni][2], o3 = acc[mi][ni][3];
            const int r0 = rbase + mi * 16 + rq;   // [0,1024)
            const int r1 = r0 + 8;
            const int p0 = cbase + ni * 8 + cq;    // even column index
            if (STAGE == 1) {
                // T'[v,p]: top v=r, bottom v=2047-r; parity-pack over p.
                const size_t pe = (size_t)(p0 >> 1);
                const size_t tb = (size_t)b * plane;
                const size_t t0 = tb + (size_t)r0 * KH + pe;
                const size_t b0 = tb + (size_t)(2047 - r0) * KH + pe;
                const size_t t1 = tb + (size_t)r1 * KH + pe;
                const size_t b1 = tb + (size_t)(2047 - r1) * KH + pe;
                put_split(Teh, Tel, t0, e4.x + o0);   // (r0, p even) top
                put_split(Toh, Tol, t0, e4.y + o1);   // (r0, p odd)  top
                put_split(Teh, Tel, b0, e4.x - o0);   // bottom
                put_split(Toh, Tol, b0, e4.y - o1);
                put_split(Teh, Tel, t1, e4.z + o2);
                put_split(Toh, Tol, t1, e4.w + o3);
                put_split(Teh, Tel, b1, e4.z - o2);
                put_split(Toh, Tol, b1, e4.w - o3);
            } else {
                // out[u,v]: top u=r -> E+O; bottom u=2047-r -> O-E. cols v.
                const size_t ob = (size_t)b * NQ * NQ;
                const size_t c = (size_t)p0;
                float2 vt0 = make_float2(e4.x + o0, e4.y + o1);
                float2 vb0 = make_float2(o0 - e4.x, o1 - e4.y);
                float2 vt1 = make_float2(e4.z + o2, e4.w + o3);
                float2 vb1 = make_float2(o2 - e4.z, o3 - e4.w);
                *(float2*)(OutF + ob + (size_t)r0 * NQ + c) = vt0;
                *(float2*)(OutF + ob + (size_t)(2047 - r0) * NQ + c) = vb0;
                *(float2*)(OutF + ob + (size_t)r1 * NQ + c) = vt1;
                *(float2*)(OutF + ob + (size_t)(2047 - r1) * NQ + c) = vb1;
            }
        }
}

// ---------------- launch ----------------
extern "C" void kernel_launch(void* const* d_in, const int* in_sizes, int n_in,
                              void* d_out, int out_size) {
    const float* x = (const float*)d_in[0];
    float* out = (float*)d_out;

    bf16 *pCeh, *pCel, *pCoh, *pCol, *pSeh, *pSel, *pSoh, *pSol;
    bf16 *pXeh, *pXel, *pXoh, *pXol, *pTeh, *pTel, *pToh, *pTol;
    cudaGetSymbolAddress((void**)&pCeh, g_Ce_h);
    cudaGetSymbolAddress((void**)&pCel, g_Ce_l);
    cudaGetSymbolAddress((void**)&pCoh, g_Co_h);
    cudaGetSymbolAddress((void**)&pCol, g_Co_l);
    cudaGetSymbolAddress((void**)&pSeh, g_Se_h);
    cudaGetSymbolAddress((void**)&pSel, g_Se_l);
    cudaGetSymbolAddress((void**)&pSoh, g_So_h);
    cudaGetSymbolAddress((void**)&pSol, g_So_l);
    cudaGetSymbolAddress((void**)&pXeh, g_Xe_h);
    cudaGetSymbolAddress((void**)&pXel, g_Xe_l);
    cudaGetSymbolAddress((void**)&pXoh, g_Xo_h);
    cudaGetSymbolAddress((void**)&pXol, g_Xo_l);
    cudaGetSymbolAddress((void**)&pTeh, g_Te_h);
    cudaGetSymbolAddress((void**)&pTel, g_Te_l);
    cudaGetSymbolAddress((void**)&pToh, g_To_h);
    cudaGetSymbolAddress((void**)&pTol, g_To_l);

    cudaFuncSetAttribute(idsct_fold_kernel<1>, cudaFuncAttributeMaxDynamicSharedMemorySize, SMEM_TOTAL);
    cudaFuncSetAttribute(idsct_fold_kernel<2>, cudaFuncAttributeMaxDynamicSharedMemorySize, SMEM_TOTAL);

    // 1) parity-packed basis + input split
    gen_basis_split<<<(KH * KH + 255) / 256, 256>>>();
    split_x<<<(int)(((size_t)NB * NQ * NQ / 8 + 255) / 256), 256>>>(x);

    // 2) Stage 1: A = Ce/Co [1024x1024], B = Xe/Xo [b,2048,1024] -> Te/To
    idsct_fold_kernel<1><<<dim3(16, 8, NB), 256, SMEM_TOTAL>>>(
        pCeh, pCel, pCoh, pCol, pXeh, pXel, pXoh, pXol,
        pTeh, pTel, pToh, pTol, nullptr);

    // 3) Stage 2: A = Se/So, B = Te/To -> out fp32
    idsct_fold_kernel<2><<<dim3(16, 8, NB), 256, SMEM_TOTAL>>>(
        pSeh, pSel, pSoh, pSol, pTeh, pTel, pToh, pTol,
        nullptr, nullptr, nullptr, nullptr, out);
}